// round 6
// baseline (speedup 1.0000x reference)
#include <cuda_runtime.h>
#include <cstdint>

#define SEQ   2048
#define DM    2048
#define NH    32
#define DH    64
#define CK    128
#define NC    16
#define BZ    4
#define MROWS (BZ*SEQ)   // 8192
#define BK    32
#define NKT   (DM/BK)    // 64

// ---------------- scratch (device globals; no allocation) ----------------
__device__ float g_xn [BZ*SEQ*DM];
__device__ float g_rx [BZ*SEQ*DM];
__device__ float g_kx [BZ*SEQ*DM];
__device__ float g_vx [BZ*SEQ*DM];
__device__ float g_r  [BZ*SEQ*DM];
__device__ float g_k  [BZ*SEQ*DM];
__device__ float g_v  [BZ*SEQ*DM];
__device__ float g_att[BZ*SEQ*DM];
__device__ float g_rkw[(size_t)BZ*NC*NH*CK*CK];
__device__ float g_wtr[DM*DM];
__device__ float g_wtk[DM*DM];
__device__ float g_wtv[DM*DM];
__device__ float g_wto[DM*DM];

// ---------------- small PTX helpers ----------------
__device__ __forceinline__ unsigned f2tf(float v)
{
    unsigned r;
    asm("cvt.rna.tf32.f32 %0, %1;" : "=r"(r) : "f"(v));
    return r;
}
__device__ __forceinline__ float roundtf(float v) { return __uint_as_float(f2tf(v)); }

__device__ __forceinline__ uint32_t smem_u32(const void* p)
{
    uint32_t a;
    asm("{ .reg .u64 t; cvta.to.shared.u64 t, %1; cvt.u32.u64 %0, t; }" : "=r"(a) : "l"(p));
    return a;
}
template<int N> __device__ __forceinline__ void cp_wait()
{
    asm volatile("cp.async.wait_group %0;" :: "n"(N) : "memory");
}
__device__ __forceinline__ void cp16(uint32_t dst, const void* src)
{
    asm volatile("cp.async.cg.shared.global [%0], [%1], 16;" :: "r"(dst), "l"(src));
}
__device__ __forceinline__ void cp_commit()
{
    asm volatile("cp.async.commit_group;" ::: "memory");
}
__device__ __forceinline__ void mma_tf32(float* c, const unsigned* a, const unsigned* b)
{
    asm volatile(
        "mma.sync.aligned.m16n8k8.row.col.f32.tf32.tf32.f32 "
        "{%0,%1,%2,%3}, {%4,%5,%6,%7}, {%8,%9}, {%0,%1,%2,%3};"
        : "+f"(c[0]), "+f"(c[1]), "+f"(c[2]), "+f"(c[3])
        : "r"(a[0]), "r"(a[1]), "r"(a[2]), "r"(a[3]),
          "r"(b[0]), "r"(b[1]));
}

// ---------------- LN over D_MODEL, also emits xn[:, -1, :] ----------------
__global__ void ln1_kernel(const float* __restrict__ x,
                           const float* __restrict__ sc,
                           const float* __restrict__ bi,
                           float* __restrict__ xlast)
{
    int row = blockIdx.x;
    const float* xr = x + (size_t)row * DM;
    float* yr = g_xn + (size_t)row * DM;
    float vals[8];
    float s = 0.f, q = 0.f;
#pragma unroll
    for (int i = 0; i < 8; i++) {
        float v = xr[threadIdx.x + i * 256];
        vals[i] = v; s += v; q += v * v;
    }
#pragma unroll
    for (int o = 16; o > 0; o >>= 1) {
        s += __shfl_xor_sync(0xffffffffu, s, o);
        q += __shfl_xor_sync(0xffffffffu, q, o);
    }
    __shared__ float rs[8], rq[8];
    int w = threadIdx.x >> 5;
    if ((threadIdx.x & 31) == 0) { rs[w] = s; rq[w] = q; }
    __syncthreads();
    s = 0.f; q = 0.f;
#pragma unroll
    for (int i = 0; i < 8; i++) { s += rs[i]; q += rq[i]; }
    float mu  = s * (1.f / DM);
    float inv = rsqrtf(q * (1.f / DM) - mu * mu + 1e-5f);
    bool last = ((row & (SEQ - 1)) == SEQ - 1);
#pragma unroll
    for (int i = 0; i < 8; i++) {
        int c = threadIdx.x + i * 256;
        float y = (vals[i] - mu) * inv * sc[c] + bi[c];
        yr[c] = y;
        if (last) xlast[(row >> 11) * DM + c] = y;
    }
}

// ---------------- token-shift mixing (outputs rounded to tf32) ----------------
__global__ void mix_kernel(const float4* __restrict__ tmr,
                           const float4* __restrict__ tmk,
                           const float4* __restrict__ tmv)
{
    long i = (long)blockIdx.x * blockDim.x + threadIdx.x;
    const float4* xn4 = (const float4*)g_xn;
    int col = (int)(i & 511);
    long t  = (i >> 9) & (SEQ - 1);
    float4 cur = xn4[i];
    float4 prv = (t == 0) ? make_float4(0.f,0.f,0.f,0.f) : xn4[i - 512];
    float4 mr = tmr[col], mk = tmk[col], mv = tmv[col];
    float4 o;
    o.x = roundtf(cur.x*mr.x + (1.f-mr.x)*prv.x);
    o.y = roundtf(cur.y*mr.y + (1.f-mr.y)*prv.y);
    o.z = roundtf(cur.z*mr.z + (1.f-mr.z)*prv.z);
    o.w = roundtf(cur.w*mr.w + (1.f-mr.w)*prv.w);
    ((float4*)g_rx)[i] = o;
    o.x = roundtf(cur.x*mk.x + (1.f-mk.x)*prv.x);
    o.y = roundtf(cur.y*mk.y + (1.f-mk.y)*prv.y);
    o.z = roundtf(cur.z*mk.z + (1.f-mk.z)*prv.z);
    o.w = roundtf(cur.w*mk.w + (1.f-mk.w)*prv.w);
    ((float4*)g_kx)[i] = o;
    o.x = roundtf(cur.x*mv.x + (1.f-mv.x)*prv.x);
    o.y = roundtf(cur.y*mv.y + (1.f-mv.y)*prv.y);
    o.z = roundtf(cur.z*mv.z + (1.f-mv.z)*prv.z);
    o.w = roundtf(cur.w*mv.w + (1.f-mv.w)*prv.w);
    ((float4*)g_vx)[i] = o;
}

// ---------------- weight transpose (and tf32 rounding) ----------------
__global__ void transpose_kernel(const float* __restrict__ src, float* __restrict__ dst)
{
    __shared__ float t[32][33];
    int bx = blockIdx.x * 32, by = blockIdx.y * 32;
#pragma unroll
    for (int i = 0; i < 4; i++)
        t[threadIdx.y + i * 8][threadIdx.x] =
            src[(size_t)(by + threadIdx.y + i * 8) * DM + bx + threadIdx.x];
    __syncthreads();
#pragma unroll
    for (int i = 0; i < 4; i++)
        dst[(size_t)(bx + threadIdx.y + i * 8) * DM + by + threadIdx.x] =
            roundtf(t[threadIdx.x][threadIdx.y + i * 8]);
}

// ---------------- tf32 mma.sync GEMM body, cp.async 3-stage, BK=32 --------
// C[8192x2048] = A @ Bt^T (+ Add). 256 thr, block 128x128x32, 8 warps 64x32.
#define ASTRIDE 36                      // floats per smem row (32 data + 4 pad)
#define STG_FLOATS (2 * 128 * ASTRIDE)  // A tile + B tile per stage = 9216 floats

__device__ __forceinline__ void gemm_body(const float* __restrict__ A,
                                          const float* __restrict__ Bt,
                                          const float* __restrict__ Add,
                                          float* __restrict__ C,
                                          int bm, int bn)
{
    extern __shared__ float smem[];
    uint32_t sb = smem_u32(smem);
    int tid = threadIdx.x, lane = tid & 31, warp = tid >> 5;
    int r0 = lane >> 2, c0 = lane & 3;
    int wm = (warp >> 2) * 64, wn = (warp & 3) * 32;

    const float* Ag = A  + (size_t)bm * DM;
    const float* Bg = Bt + (size_t)bn * DM;

    int cm = tid >> 1, cko = (tid & 1) * 16;   // copy: row, k-offset (16 floats each)
    auto copy_stage = [&](int buf, int kt) {
        uint32_t sA = sb + buf * (STG_FLOATS * 4);
        uint32_t sB = sA + 128 * ASTRIDE * 4;
        const float* Ac = Ag + kt * BK + (size_t)cm * DM + cko;
        const float* Bc = Bg + kt * BK + (size_t)cm * DM + cko;
        uint32_t off = cm * (ASTRIDE * 4) + cko * 4;
#pragma unroll
        for (int q = 0; q < 4; q++) {
            cp16(sA + off + q * 16, Ac + q * 4);
            cp16(sB + off + q * 16, Bc + q * 4);
        }
        cp_commit();
    };

    float acc[4][4][4];
#pragma unroll
    for (int i = 0; i < 4; i++)
#pragma unroll
        for (int j = 0; j < 4; j++)
#pragma unroll
            for (int e = 0; e < 4; e++) acc[i][j][e] = 0.f;

    copy_stage(0, 0);
    copy_stage(1, 1);
    cp_wait<1>();
    __syncthreads();

    for (int kt = 0; kt < NKT; kt++) {
        int buf = kt % 3;
        const float* As = smem + buf * STG_FLOATS;
        const float* Bs = As + 128 * ASTRIDE;
#pragma unroll
        for (int ks = 0; ks < 4; ks++) {
            int k0 = ks * 8;
            unsigned af[4][4], bf[4][2];
#pragma unroll
            for (int i = 0; i < 4; i++) {
                int m0 = (wm + i * 16 + r0) * ASTRIDE + k0 + c0;
                af[i][0] = __float_as_uint(As[m0]);
                af[i][1] = __float_as_uint(As[m0 + 8 * ASTRIDE]);
                af[i][2] = __float_as_uint(As[m0 + 4]);
                af[i][3] = __float_as_uint(As[m0 + 8 * ASTRIDE + 4]);
            }
#pragma unroll
            for (int j = 0; j < 4; j++) {
                int n0 = (wn + j * 8 + r0) * ASTRIDE + k0 + c0;
                bf[j][0] = __float_as_uint(Bs[n0]);
                bf[j][1] = __float_as_uint(Bs[n0 + 4]);
            }
#pragma unroll
            for (int i = 0; i < 4; i++)
#pragma unroll
                for (int j = 0; j < 4; j++)
                    mma_tf32(acc[i][j], af[i], bf[j]);
        }
        // one commit-group per iteration (empty in tail) keeps wait<1>'s
        // "next tile resident" invariant through the last iterations
        if (kt + 2 < NKT) copy_stage((kt + 2) % 3, kt + 2);
        else              cp_commit();
        cp_wait<1>();
        __syncthreads();
    }

#pragma unroll
    for (int i = 0; i < 4; i++) {
        int row = bm + wm + i * 16 + r0;
#pragma unroll
        for (int j = 0; j < 4; j++) {
            int col = bn + wn + j * 8 + c0 * 2;
            size_t o0 = (size_t)row * DM + col;
            size_t o1 = (size_t)(row + 8) * DM + col;
            float2 v0 = make_float2(acc[i][j][0], acc[i][j][1]);
            float2 v1 = make_float2(acc[i][j][2], acc[i][j][3]);
            if (Add) {
                float2 a0 = *(const float2*)(Add + o0);
                float2 a1 = *(const float2*)(Add + o1);
                v0.x += a0.x; v0.y += a0.y;
                v1.x += a1.x; v1.y += a1.y;
            }
            *(float2*)(C + o0) = v0;
            *(float2*)(C + o1) = v1;
        }
    }
}

// fused r/k/v projections: gridDim.z selects which GEMM (one launch, one tail)
__global__ void __launch_bounds__(256, 2) rkv_gemm_kernel(const float* __restrict__ wtr,
                                                          const float* __restrict__ wtk,
                                                          const float* __restrict__ wtv)
{
    int z = blockIdx.z;
    const float* A  = (z == 0) ? g_rx : (z == 1) ? g_kx : g_vx;
    const float* Bt = (z == 0) ? wtr  : (z == 1) ? wtk  : wtv;
    float* C        = (z == 0) ? g_r  : (z == 1) ? g_k  : g_v;
    gemm_body(A, Bt, nullptr, C, blockIdx.y * 128, blockIdx.x * 128);
}

__global__ void __launch_bounds__(256, 2) out_gemm_kernel(const float* __restrict__ wto,
                                                          const float* __restrict__ Add,
                                                          float* __restrict__ Out)
{
    gemm_body(g_att, wto, Add, Out, blockIdx.y * 128, blockIdx.x * 128);
}

// ---------------- rkw = (r @ k^T) * mask, per (b,chunk,head), 64x64 tiles --
__global__ void rkw_kernel(const float* __restrict__ tdcy,
                           const float* __restrict__ tfirst)
{
    int jt = blockIdx.x, it = blockIdx.y, bch = blockIdx.z;
    int h = bch & 31;
    int chunk = (bch >> 5) & 15;
    int b = bch >> 9;
    __shared__ float rs[64][68];
    __shared__ float ks[64][68];
    int tid = threadIdx.x;
    int lrow = tid >> 2;
    int lc4  = (tid & 3) * 16;
    size_t rbase = ((size_t)(b*SEQ + chunk*CK + it*64 + lrow)) * DM + h*64 + lc4;
    size_t kbase = ((size_t)(b*SEQ + chunk*CK + jt*64 + lrow)) * DM + h*64 + lc4;
#pragma unroll
    for (int m = 0; m < 4; m++) {
        float4 rv = *(const float4*)(g_r + rbase + m * 4);
        float4 kv = *(const float4*)(g_k + kbase + m * 4);
        int d = lc4 + m * 4;
        rs[d+0][lrow] = rv.x; rs[d+1][lrow] = rv.y; rs[d+2][lrow] = rv.z; rs[d+3][lrow] = rv.w;
        ks[d+0][lrow] = kv.x; ks[d+1][lrow] = kv.y; ks[d+2][lrow] = kv.z; ks[d+3][lrow] = kv.w;
    }
    __syncthreads();
    int tx = tid & 15, ty = tid >> 4;
    float acc[4][4] = {};
#pragma unroll 8
    for (int d = 0; d < 64; d++) {
        float4 a = *(const float4*)&rs[d][ty * 4];
        float4 bq = *(const float4*)&ks[d][tx * 4];
        float ar[4] = {a.x,a.y,a.z,a.w};
        float br[4] = {bq.x,bq.y,bq.z,bq.w};
#pragma unroll
        for (int x = 0; x < 4; x++)
#pragma unroll
            for (int y = 0; y < 4; y++)
                acc[x][y] += ar[x] * br[y];
    }
    float logw = -expf(tdcy[h]);
    float u    =  expf(tfirst[h]);
#pragma unroll
    for (int x = 0; x < 4; x++)
#pragma unroll
        for (int y = 0; y < 4; y++) {
            int i = it * 64 + ty * 4 + x;
            int j = jt * 64 + tx * 4 + y;
            float m;
            if (i > j)      m = expf(logw * (float)(i - j - 1));
            else if (i == j) m = u;
            else             m = 0.f;
            g_rkw[((size_t)bch * CK + i) * CK + j] = acc[x][y] * m;
        }
}

// ---------------- sep = rkw @ v, per (b,chunk,head) ----------------
__global__ void sep_kernel()
{
    int bch = blockIdx.x;
    int h = bch & 31;
    int chunk = (bch >> 5) & 15;
    int b = bch >> 9;
    int tid = threadIdx.x;
    __shared__ float vs[128][64];
    __shared__ float rk[16][132];
    {
        int row = tid >> 1, e0 = (tid & 1) * 32;
        size_t base = ((size_t)(b*SEQ + chunk*CK + row)) * DM + h*64 + e0;
#pragma unroll
        for (int m = 0; m < 8; m++)
            *(float4*)&vs[row][e0 + m * 4] = *(const float4*)(g_v + base + m * 4);
    }
    int ty = tid >> 3, tx = tid & 7;
    float acc[4][8] = {};
    int rrow = tid >> 1, jc = (tid & 1) * 8;
    for (int s = 0; s < 8; s++) {
        const float* src = g_rkw + ((size_t)bch * CK + rrow) * CK + s * 16 + jc;
        float4 r0 = *(const float4*)src;
        float4 r1 = *(const float4*)(src + 4);
        __syncthreads();
        rk[jc+0][rrow] = r0.x; rk[jc+1][rrow] = r0.y; rk[jc+2][rrow] = r0.z; rk[jc+3][rrow] = r0.w;
        rk[jc+4][rrow] = r1.x; rk[jc+5][rrow] = r1.y; rk[jc+6][rrow] = r1.z; rk[jc+7][rrow] = r1.w;
        __syncthreads();
#pragma unroll
        for (int jj = 0; jj < 16; jj++) {
            float4 a  = *(const float4*)&rk[jj][ty * 4];
            float4 b0 = *(const float4*)&vs[s * 16 + jj][tx * 8];
            float4 b1 = *(const float4*)&vs[s * 16 + jj][tx * 8 + 4];
            float ar[4] = {a.x,a.y,a.z,a.w};
            float br[8] = {b0.x,b0.y,b0.z,b0.w,b1.x,b1.y,b1.z,b1.w};
#pragma unroll
            for (int x = 0; x < 4; x++)
#pragma unroll
                for (int e = 0; e < 8; e++)
                    acc[x][e] += ar[x] * br[e];
        }
    }
    size_t obase = ((size_t)(b*SEQ + chunk*CK)) * DM + h*64;
#pragma unroll
    for (int x = 0; x < 4; x++) {
        size_t ro = obase + (size_t)(ty * 4 + x) * DM + tx * 8;
        float4 o0, o1;
        o0.x = acc[x][0]; o0.y = acc[x][1]; o0.z = acc[x][2]; o0.w = acc[x][3];
        o1.x = acc[x][4]; o1.y = acc[x][5]; o1.z = acc[x][6]; o1.w = acc[x][7];
        *(float4*)(g_att + ro)     = o0;
        *(float4*)(g_att + ro + 4) = o1;
    }
}

// ---------------- sequential chunk scan per (b,head) ----------------
__global__ void scan_kernel(const float* __restrict__ tdcy,
                            float* __restrict__ state_out)
{
    int bh = blockIdx.x;
    int h = bh & 31, b = bh >> 5;
    int tid = threadIdx.x;
    __shared__ float state[64][65];
    __shared__ float bufA[32][68];
    __shared__ float bufB[32][68];
    float logw = -expf(tdcy[h]);
    float wC = expf(logw * 128.f);
    for (int idx = tid; idx < 64 * 64; idx += 256)
        state[idx >> 6][idx & 63] = 0.f;
    __syncthreads();
    int lrow = tid >> 3, lcol = (tid & 7) * 8;
    int td = (tid >> 4) * 4, te2 = (tid & 15) * 4;
    for (int c = 0; c < NC; c++) {
        size_t base = ((size_t)(b*SEQ + c*CK)) * DM + h * 64;
        for (int s4 = 0; s4 < 4; s4++) {
            const float* src = g_r + base + (size_t)(s4 * 32 + lrow) * DM + lcol;
            float4 v0 = *(const float4*)src;
            float4 v1 = *(const float4*)(src + 4);
            *(float4*)&bufA[lrow][lcol]     = v0;
            *(float4*)&bufA[lrow][lcol + 4] = v1;
            __syncthreads();
            float acc[8] = {};
            int ti = tid >> 3, te = (tid & 7) * 8;
#pragma unroll 8
            for (int d = 0; d < 64; d++) {
                float rv = bufA[ti][d];
#pragma unroll
                for (int e = 0; e < 8; e++)
                    acc[e] += rv * state[d][te + e];
            }
            float wi = expf(logw * (float)(s4 * 32 + ti));
            float* dst = g_att + base + (size_t)(s4 * 32 + ti) * DM + te;
            float4 o0 = *(float4*)dst;
            float4 o1 = *(float4*)(dst + 4);
            o0.x += wi * acc[0]; o0.y += wi * acc[1]; o0.z += wi * acc[2]; o0.w += wi * acc[3];
            o1.x += wi * acc[4]; o1.y += wi * acc[5]; o1.z += wi * acc[6]; o1.w += wi * acc[7];
            *(float4*)dst = o0;
            *(float4*)(dst + 4) = o1;
            __syncthreads();
        }
        float sacc[4][4] = {};
        for (int s4 = 0; s4 < 4; s4++) {
            int j = s4 * 32 + lrow;
            float wk = expf(logw * (float)(127 - j));
            const float* ksrc = g_k + base + (size_t)j * DM + lcol;
            const float* vsrc = g_v + base + (size_t)j * DM + lcol;
            float4 k0 = *(const float4*)ksrc;
            float4 k1 = *(const float4*)(ksrc + 4);
            float4 w0 = *(const float4*)vsrc;
            float4 w1 = *(const float4*)(vsrc + 4);
            k0.x *= wk; k0.y *= wk; k0.z *= wk; k0.w *= wk;
            k1.x *= wk; k1.y *= wk; k1.z *= wk; k1.w *= wk;
            *(float4*)&bufA[lrow][lcol]     = k0;
            *(float4*)&bufA[lrow][lcol + 4] = k1;
            *(float4*)&bufB[lrow][lcol]     = w0;
            *(float4*)&bufB[lrow][lcol + 4] = w1;
            __syncthreads();
#pragma unroll 4
            for (int jj = 0; jj < 32; jj++) {
                float4 ka = *(const float4*)&bufA[jj][td];
                float4 vb = *(const float4*)&bufB[jj][te2];
                float ar[4] = {ka.x,ka.y,ka.z,ka.w};
                float br[4] = {vb.x,vb.y,vb.z,vb.w};
#pragma unroll
                for (int x = 0; x < 4; x++)
#pragma unroll
                    for (int y = 0; y < 4; y++)
                        sacc[x][y] += ar[x] * br[y];
            }
            __syncthreads();
        }
#pragma unroll
        for (int x = 0; x < 4; x++)
#pragma unroll
            for (int y = 0; y < 4; y++)
                state[td + x][te2 + y] = state[td + x][te2 + y] * wC + sacc[x][y];
        __syncthreads();
    }
    for (int idx = tid; idx < 4096; idx += 256) {
        int d = idx >> 6, e = idx & 63;
        state_out[((size_t)(b * NH + h) * 64 + d) * 64 + e] = state[d][e];
    }
}

// ---------------- per-head LN (in place on g_att, output rounded to tf32) ----
__global__ void lnx_kernel(const float* __restrict__ sc,
                           const float* __restrict__ bi)
{
    int w = blockIdx.x * 8 + (threadIdx.x >> 5);
    int lid = threadIdx.x & 31;
    int h = w & 31;
    size_t row = (size_t)(w >> 5);
    float* p = g_att + row * DM + h * 64;
    float x0 = p[lid], x1 = p[lid + 32];
    float s = x0 + x1, q = x0 * x0 + x1 * x1;
#pragma unroll
    for (int o = 16; o > 0; o >>= 1) {
        s += __shfl_xor_sync(0xffffffffu, s, o);
        q += __shfl_xor_sync(0xffffffffu, q, o);
    }
    float mu  = s * (1.f / 64.f);
    float inv = rsqrtf(q * (1.f / 64.f) - mu * mu + 1e-5f);
    p[lid]      = roundtf((x0 - mu) * inv * sc[h * 64 + lid]      + bi[h * 64 + lid]);
    p[lid + 32] = roundtf((x1 - mu) * inv * sc[h * 64 + lid + 32] + bi[h * 64 + lid + 32]);
}

// ---------------- launch ----------------
extern "C" void kernel_launch(void* const* d_in, const int* in_sizes, int n_in,
                              void* d_out, int out_size)
{
    const float* inputs = (const float*)d_in[0];
    const float* tmr    = (const float*)d_in[1];
    const float* tmk    = (const float*)d_in[2];
    const float* tmv    = (const float*)d_in[3];
    const float* Wk     = (const float*)d_in[4];
    const float* Wv     = (const float*)d_in[5];
    const float* Wr     = (const float*)d_in[6];
    const float* Wo     = (const float*)d_in[7];
    const float* tdcy   = (const float*)d_in[8];
    const float* tfirst = (const float*)d_in[9];
    const float* ln1s   = (const float*)d_in[10];
    const float* ln1b   = (const float*)d_in[11];
    const float* lnxs   = (const float*)d_in[12];
    const float* lnxb   = (const float*)d_in[13];

    float* out0      = (float*)d_out;
    float* out_xlast = out0 + (size_t)BZ * SEQ * DM;
    float* out_state = out_xlast + (size_t)BZ * DM;

    const int GSMEM = 3 * STG_FLOATS * 4;   // 110592 B
    cudaFuncSetAttribute(rkv_gemm_kernel, cudaFuncAttributeMaxDynamicSharedMemorySize, GSMEM);
    cudaFuncSetAttribute(out_gemm_kernel, cudaFuncAttributeMaxDynamicSharedMemorySize, GSMEM);

    float* wtr; float* wtk; float* wtv; float* wto;
    cudaGetSymbolAddress((void**)&wtr, g_wtr);
    cudaGetSymbolAddress((void**)&wtk, g_wtk);
    cudaGetSymbolAddress((void**)&wtv, g_wtv);
    cudaGetSymbolAddress((void**)&wto, g_wto);

    dim3 tg(64, 64), tb(32, 8);
    transpose_kernel<<<tg, tb>>>(Wr, wtr);
    transpose_kernel<<<tg, tb>>>(Wk, wtk);
    transpose_kernel<<<tg, tb>>>(Wv, wtv);
    transpose_kernel<<<tg, tb>>>(Wo, wto);

    ln1_kernel<<<MROWS, 256>>>(inputs, ln1s, ln1b, out_xlast);
    mix_kernel<<<(MROWS * (DM / 4)) / 256, 256>>>((const float4*)tmr,
                                                  (const float4*)tmk,
                                                  (const float4*)tmv);
    rkv_gemm_kernel<<<dim3(DM / 128, MROWS / 128, 3), 256, GSMEM>>>(wtr, wtk, wtv);
    rkw_kernel<<<dim3(2, 2, BZ * NC * NH), 256>>>(tdcy, tfirst);
    sep_kernel<<<BZ * NC * NH, 256>>>();
    scan_kernel<<<BZ * NH, 256>>>(tdcy, out_state);
    lnx_kernel<<<(MROWS * NH) / 8, 256>>>(lnxs, lnxb);
    out_gemm_kernel<<<dim3(DM / 128, MROWS / 128), 256, GSMEM>>>(wto, inputs, out0);
}

// round 7
// speedup vs baseline: 1.0750x; 1.0750x over previous
#include <cuda_runtime.h>
#include <cstdint>

#define SEQ   2048
#define DM    2048
#define NH    32
#define DH    64
#define CK    128
#define NC    16
#define BZ    4
#define MROWS (BZ*SEQ)   // 8192
#define BK    16
#define NKT   (DM/BK)    // 128

// ---------------- scratch (device globals; no allocation) ----------------
__device__ float g_rx [BZ*SEQ*DM];
__device__ float g_kx [BZ*SEQ*DM];
__device__ float g_vx [BZ*SEQ*DM];
__device__ float g_r  [BZ*SEQ*DM];
__device__ float g_k  [BZ*SEQ*DM];
__device__ float g_v  [BZ*SEQ*DM];
__device__ float g_att[BZ*SEQ*DM];
__device__ float g_rkw[(size_t)BZ*NC*NH*CK*CK];
__device__ float g_wtr[DM*DM];
__device__ float g_wtk[DM*DM];
__device__ float g_wtv[DM*DM];
__device__ float g_wto[DM*DM];

// ---------------- small PTX helpers ----------------
__device__ __forceinline__ unsigned f2tf(float v)
{
    unsigned r;
    asm("cvt.rna.tf32.f32 %0, %1;" : "=r"(r) : "f"(v));
    return r;
}
__device__ __forceinline__ float roundtf(float v) { return __uint_as_float(f2tf(v)); }

__device__ __forceinline__ uint32_t smem_u32(const void* p)
{
    uint32_t a;
    asm("{ .reg .u64 t; cvta.to.shared.u64 t, %1; cvt.u32.u64 %0, t; }" : "=r"(a) : "l"(p));
    return a;
}
template<int N> __device__ __forceinline__ void cp_wait()
{
    asm volatile("cp.async.wait_group %0;" :: "n"(N) : "memory");
}
__device__ __forceinline__ void cp16(uint32_t dst, const void* src)
{
    asm volatile("cp.async.cg.shared.global [%0], [%1], 16;" :: "r"(dst), "l"(src));
}
__device__ __forceinline__ void cp_commit()
{
    asm volatile("cp.async.commit_group;" ::: "memory");
}
__device__ __forceinline__ void mma_tf32(float* c, const unsigned* a, const unsigned* b)
{
    asm volatile(
        "mma.sync.aligned.m16n8k8.row.col.f32.tf32.tf32.f32 "
        "{%0,%1,%2,%3}, {%4,%5,%6,%7}, {%8,%9}, {%0,%1,%2,%3};"
        : "+f"(c[0]), "+f"(c[1]), "+f"(c[2]), "+f"(c[3])
        : "r"(a[0]), "r"(a[1]), "r"(a[2]), "r"(a[3]),
          "r"(b[0]), "r"(b[1]));
}

// ---------------- fused LN + token-shift mixing ----------------
// Recomputes LN(row-1) in-block (same op order as LN(row) => identical bits),
// eliminating the g_xn staging array entirely.
__global__ void lnmix_kernel(const float* __restrict__ x,
                             const float* __restrict__ sc,
                             const float* __restrict__ bi,
                             const float* __restrict__ tmr,
                             const float* __restrict__ tmk,
                             const float* __restrict__ tmv,
                             float* __restrict__ xlast)
{
    int row = blockIdx.x;
    int t   = row & (SEQ - 1);
    const float* xr = x + (size_t)row * DM;
    float cur[8], prv[8];
    float s0 = 0.f, q0 = 0.f, s1 = 0.f, q1 = 0.f;
#pragma unroll
    for (int i = 0; i < 8; i++) {
        int c = threadIdx.x + i * 256;
        float v = xr[c];
        cur[i] = v; s0 += v; q0 += v * v;
        float u = t ? xr[c - DM] : 0.f;
        prv[i] = u; s1 += u; q1 += u * u;
    }
#pragma unroll
    for (int o = 16; o > 0; o >>= 1) {
        s0 += __shfl_xor_sync(0xffffffffu, s0, o);
        q0 += __shfl_xor_sync(0xffffffffu, q0, o);
        s1 += __shfl_xor_sync(0xffffffffu, s1, o);
        q1 += __shfl_xor_sync(0xffffffffu, q1, o);
    }
    __shared__ float rs0[8], rq0[8], rs1[8], rq1[8];
    int w = threadIdx.x >> 5;
    if ((threadIdx.x & 31) == 0) { rs0[w] = s0; rq0[w] = q0; rs1[w] = s1; rq1[w] = q1; }
    __syncthreads();
    s0 = 0.f; q0 = 0.f; s1 = 0.f; q1 = 0.f;
#pragma unroll
    for (int i = 0; i < 8; i++) { s0 += rs0[i]; q0 += rq0[i]; s1 += rs1[i]; q1 += rq1[i]; }
    float mu0  = s0 * (1.f / DM);
    float inv0 = rsqrtf(q0 * (1.f / DM) - mu0 * mu0 + 1e-5f);
    float mu1  = s1 * (1.f / DM);
    float inv1 = rsqrtf(q1 * (1.f / DM) - mu1 * mu1 + 1e-5f);
    bool last = (t == SEQ - 1);
#pragma unroll
    for (int i = 0; i < 8; i++) {
        int c = threadIdx.x + i * 256;
        float yc = (cur[i] - mu0) * inv0 * sc[c] + bi[c];
        float yp = t ? (prv[i] - mu1) * inv1 * sc[c] + bi[c] : 0.f;
        size_t off = (size_t)row * DM + c;
        float mr = tmr[c], mk = tmk[c], mv = tmv[c];
        g_rx[off] = roundtf(yc * mr + (1.f - mr) * yp);
        g_kx[off] = roundtf(yc * mk + (1.f - mk) * yp);
        g_vx[off] = roundtf(yc * mv + (1.f - mv) * yp);
        if (last) xlast[(row >> 11) * DM + c] = yc;
    }
}

// ---------------- 4 weight transposes in one launch (tf32 rounding) --------
__global__ void transpose4_kernel(const float* __restrict__ s0, float* __restrict__ d0,
                                  const float* __restrict__ s1, float* __restrict__ d1,
                                  const float* __restrict__ s2, float* __restrict__ d2,
                                  const float* __restrict__ s3, float* __restrict__ d3)
{
    const float* src; float* dst;
    switch (blockIdx.z) {
        case 0:  src = s0; dst = d0; break;
        case 1:  src = s1; dst = d1; break;
        case 2:  src = s2; dst = d2; break;
        default: src = s3; dst = d3; break;
    }
    __shared__ float t[32][33];
    int bx = blockIdx.x * 32, by = blockIdx.y * 32;
#pragma unroll
    for (int i = 0; i < 4; i++)
        t[threadIdx.y + i * 8][threadIdx.x] =
            src[(size_t)(by + threadIdx.y + i * 8) * DM + bx + threadIdx.x];
    __syncthreads();
#pragma unroll
    for (int i = 0; i < 4; i++)
        dst[(size_t)(bx + threadIdx.y + i * 8) * DM + by + threadIdx.x] =
            roundtf(t[threadIdx.x][threadIdx.y + i * 8]);
}

// ---------------- tf32 mma.sync GEMM, cp.async 4-stage, BK=16 ----------
// C[8192x2048] = A @ Bt^T   (A row-major [m][k], Bt row-major [n][k], tf32-rounded)
// 256 threads, block tile 128x128x16, 8 warps as 2(m) x 4(n) -> warp tile 64x32
#define ASTRIDE 20                      // floats per smem row (16 data + 4 pad)
#define STG_FLOATS (2 * 128 * ASTRIDE)  // A tile + B tile per stage = 5120 floats

template<int MODE>
__global__ void __launch_bounds__(256, 2) tgemm_kernel(const float* __restrict__ Bt,
                                                       const float* __restrict__ Add,
                                                       float* __restrict__ Out)
{
    const float* A;
    float* C;
    if constexpr (MODE == 0) { A = g_rx; C = g_r; }
    else if constexpr (MODE == 1) { A = g_kx; C = g_k; }
    else if constexpr (MODE == 2) { A = g_vx; C = g_v; }
    else { A = g_att; C = Out; }

    extern __shared__ float smem[];
    uint32_t sb = smem_u32(smem);
    int tid = threadIdx.x, lane = tid & 31, warp = tid >> 5;
    int r0 = lane >> 2, c0 = lane & 3;
    int wm = (warp >> 2) * 64, wn = (warp & 3) * 32;
    int bm = blockIdx.y * 128, bn = blockIdx.x * 128;

    const float* Ag = A  + (size_t)bm * DM;
    const float* Bg = Bt + (size_t)bn * DM;

    int cm = tid >> 1, cko = (tid & 1) * 8;   // copy: row, k-offset
    auto copy_stage = [&](int buf, int kt) {
        uint32_t sA = sb + buf * (STG_FLOATS * 4);
        uint32_t sB = sA + 128 * ASTRIDE * 4;
        const float* Ac = Ag + kt * BK + (size_t)cm * DM + cko;
        const float* Bc = Bg + kt * BK + (size_t)cm * DM + cko;
        uint32_t off = cm * (ASTRIDE * 4) + cko * 4;
        cp16(sA + off,      Ac);
        cp16(sA + off + 16, Ac + 4);
        cp16(sB + off,      Bc);
        cp16(sB + off + 16, Bc + 4);
        cp_commit();
    };

    float acc[4][4][4];
#pragma unroll
    for (int i = 0; i < 4; i++)
#pragma unroll
        for (int j = 0; j < 4; j++)
#pragma unroll
            for (int e = 0; e < 4; e++) acc[i][j][e] = 0.f;

    copy_stage(0, 0);
    copy_stage(1, 1);
    copy_stage(2, 2);
    cp_wait<2>();
    __syncthreads();

    for (int kt = 0; kt < NKT; kt++) {
        int buf = kt & 3;
        const float* As = smem + buf * STG_FLOATS;
        const float* Bs = As + 128 * ASTRIDE;
#pragma unroll
        for (int ks = 0; ks < 2; ks++) {
            int k0 = ks * 8;
            unsigned af[4][4], bf[4][2];
#pragma unroll
            for (int i = 0; i < 4; i++) {
                int m0 = (wm + i * 16 + r0) * ASTRIDE + k0 + c0;
                af[i][0] = __float_as_uint(As[m0]);
                af[i][1] = __float_as_uint(As[m0 + 8 * ASTRIDE]);
                af[i][2] = __float_as_uint(As[m0 + 4]);
                af[i][3] = __float_as_uint(As[m0 + 8 * ASTRIDE + 4]);
            }
#pragma unroll
            for (int j = 0; j < 4; j++) {
                int n0 = (wn + j * 8 + r0) * ASTRIDE + k0 + c0;
                bf[j][0] = __float_as_uint(Bs[n0]);
                bf[j][1] = __float_as_uint(Bs[n0 + 4]);
            }
#pragma unroll
            for (int i = 0; i < 4; i++)
#pragma unroll
                for (int j = 0; j < 4; j++)
                    mma_tf32(acc[i][j], af[i], bf[j]);
        }
        // one commit-group per iteration (empty in tail): wait<2> then always
        // guarantees tile kt+1 resident at the next iteration
        if (kt + 3 < NKT) copy_stage((kt + 3) & 3, kt + 3);
        else              cp_commit();
        cp_wait<2>();
        __syncthreads();
    }

    // epilogue: direct register -> global (float2 per mma half-row)
#pragma unroll
    for (int i = 0; i < 4; i++) {
        int row = bm + wm + i * 16 + r0;
#pragma unroll
        for (int j = 0; j < 4; j++) {
            int col = bn + wn + j * 8 + c0 * 2;
            size_t o0 = (size_t)row * DM + col;
            size_t o1 = (size_t)(row + 8) * DM + col;
            float2 v0 = make_float2(acc[i][j][0], acc[i][j][1]);
            float2 v1 = make_float2(acc[i][j][2], acc[i][j][3]);
            if constexpr (MODE == 3) {
                float2 a0 = *(const float2*)(Add + o0);
                float2 a1 = *(const float2*)(Add + o1);
                v0.x += a0.x; v0.y += a0.y;
                v1.x += a1.x; v1.y += a1.y;
            }
            *(float2*)(C + o0) = v0;
            *(float2*)(C + o1) = v1;
        }
    }
}

// ---------------- rkw = (r @ k^T) * mask, per (b,chunk,head), 64x64 tiles --
__global__ void rkw_kernel(const float* __restrict__ tdcy,
                           const float* __restrict__ tfirst)
{
    int jt = blockIdx.x, it = blockIdx.y, bch = blockIdx.z;
    int h = bch & 31;
    int chunk = (bch >> 5) & 15;
    int b = bch >> 9;
    __shared__ float rs[64][68];
    __shared__ float ks[64][68];
    int tid = threadIdx.x;
    int lrow = tid >> 2;
    int lc4  = (tid & 3) * 16;
    size_t rbase = ((size_t)(b*SEQ + chunk*CK + it*64 + lrow)) * DM + h*64 + lc4;
    size_t kbase = ((size_t)(b*SEQ + chunk*CK + jt*64 + lrow)) * DM + h*64 + lc4;
#pragma unroll
    for (int m = 0; m < 4; m++) {
        float4 rv = *(const float4*)(g_r + rbase + m * 4);
        float4 kv = *(const float4*)(g_k + kbase + m * 4);
        int d = lc4 + m * 4;
        rs[d+0][lrow] = rv.x; rs[d+1][lrow] = rv.y; rs[d+2][lrow] = rv.z; rs[d+3][lrow] = rv.w;
        ks[d+0][lrow] = kv.x; ks[d+1][lrow] = kv.y; ks[d+2][lrow] = kv.z; ks[d+3][lrow] = kv.w;
    }
    __syncthreads();
    int tx = tid & 15, ty = tid >> 4;
    float acc[4][4] = {};
#pragma unroll 8
    for (int d = 0; d < 64; d++) {
        float4 a = *(const float4*)&rs[d][ty * 4];
        float4 bq = *(const float4*)&ks[d][tx * 4];
        float ar[4] = {a.x,a.y,a.z,a.w};
        float br[4] = {bq.x,bq.y,bq.z,bq.w};
#pragma unroll
        for (int x = 0; x < 4; x++)
#pragma unroll
            for (int y = 0; y < 4; y++)
                acc[x][y] += ar[x] * br[y];
    }
    float logw = -expf(tdcy[h]);
    float u    =  expf(tfirst[h]);
#pragma unroll
    for (int x = 0; x < 4; x++)
#pragma unroll
        for (int y = 0; y < 4; y++) {
            int i = it * 64 + ty * 4 + x;
            int j = jt * 64 + tx * 4 + y;
            float m;
            if (i > j)      m = expf(logw * (float)(i - j - 1));
            else if (i == j) m = u;
            else             m = 0.f;
            g_rkw[((size_t)bch * CK + i) * CK + j] = acc[x][y] * m;
        }
}

// ---------------- sep = rkw @ v, per (b,chunk,head) ----------------
__global__ void sep_kernel()
{
    int bch = blockIdx.x;
    int h = bch & 31;
    int chunk = (bch >> 5) & 15;
    int b = bch >> 9;
    int tid = threadIdx.x;
    __shared__ float vs[128][64];
    __shared__ float rk[16][132];
    {
        int row = tid >> 1, e0 = (tid & 1) * 32;
        size_t base = ((size_t)(b*SEQ + chunk*CK + row)) * DM + h*64 + e0;
#pragma unroll
        for (int m = 0; m < 8; m++)
            *(float4*)&vs[row][e0 + m * 4] = *(const float4*)(g_v + base + m * 4);
    }
    int ty = tid >> 3, tx = tid & 7;
    float acc[4][8] = {};
    int rrow = tid >> 1, jc = (tid & 1) * 8;
    for (int s = 0; s < 8; s++) {
        const float* src = g_rkw + ((size_t)bch * CK + rrow) * CK + s * 16 + jc;
        float4 r0 = *(const float4*)src;
        float4 r1 = *(const float4*)(src + 4);
        __syncthreads();
        rk[jc+0][rrow] = r0.x; rk[jc+1][rrow] = r0.y; rk[jc+2][rrow] = r0.z; rk[jc+3][rrow] = r0.w;
        rk[jc+4][rrow] = r1.x; rk[jc+5][rrow] = r1.y; rk[jc+6][rrow] = r1.z; rk[jc+7][rrow] = r1.w;
        __syncthreads();
#pragma unroll
        for (int jj = 0; jj < 16; jj++) {
            float4 a  = *(const float4*)&rk[jj][ty * 4];
            float4 b0 = *(const float4*)&vs[s * 16 + jj][tx * 8];
            float4 b1 = *(const float4*)&vs[s * 16 + jj][tx * 8 + 4];
            float ar[4] = {a.x,a.y,a.z,a.w};
            float br[8] = {b0.x,b0.y,b0.z,b0.w,b1.x,b1.y,b1.z,b1.w};
#pragma unroll
            for (int x = 0; x < 4; x++)
#pragma unroll
                for (int e = 0; e < 8; e++)
                    acc[x][e] += ar[x] * br[e];
        }
    }
    size_t obase = ((size_t)(b*SEQ + chunk*CK)) * DM + h*64;
#pragma unroll
    for (int x = 0; x < 4; x++) {
        size_t ro = obase + (size_t)(ty * 4 + x) * DM + tx * 8;
        float4 o0, o1;
        o0.x = acc[x][0]; o0.y = acc[x][1]; o0.z = acc[x][2]; o0.w = acc[x][3];
        o1.x = acc[x][4]; o1.y = acc[x][5]; o1.z = acc[x][6]; o1.w = acc[x][7];
        *(float4*)(g_att + ro)     = o0;
        *(float4*)(g_att + ro + 4) = o1;
    }
}

// ---------------- sequential chunk scan per (b,head) ----------------
__global__ void scan_kernel(const float* __restrict__ tdcy,
                            float* __restrict__ state_out)
{
    int bh = blockIdx.x;
    int h = bh & 31, b = bh >> 5;
    int tid = threadIdx.x;
    __shared__ float state[64][65];
    __shared__ float bufA[32][68];
    __shared__ float bufB[32][68];
    float logw = -expf(tdcy[h]);
    float wC = expf(logw * 128.f);
    for (int idx = tid; idx < 64 * 64; idx += 256)
        state[idx >> 6][idx & 63] = 0.f;
    __syncthreads();
    int lrow = tid >> 3, lcol = (tid & 7) * 8;
    int td = (tid >> 4) * 4, te2 = (tid & 15) * 4;
    for (int c = 0; c < NC; c++) {
        size_t base = ((size_t)(b*SEQ + c*CK)) * DM + h * 64;
        for (int s4 = 0; s4 < 4; s4++) {
            const float* src = g_r + base + (size_t)(s4 * 32 + lrow) * DM + lcol;
            float4 v0 = *(const float4*)src;
            float4 v1 = *(const float4*)(src + 4);
            *(float4*)&bufA[lrow][lcol]     = v0;
            *(float4*)&bufA[lrow][lcol + 4] = v1;
            __syncthreads();
            float acc[8] = {};
            int ti = tid >> 3, te = (tid & 7) * 8;
#pragma unroll 8
            for (int d = 0; d < 64; d++) {
                float rv = bufA[ti][d];
#pragma unroll
                for (int e = 0; e < 8; e++)
                    acc[e] += rv * state[d][te + e];
            }
            float wi = expf(logw * (float)(s4 * 32 + ti));
            float* dst = g_att + base + (size_t)(s4 * 32 + ti) * DM + te;
            float4 o0 = *(float4*)dst;
            float4 o1 = *(float4*)(dst + 4);
            o0.x += wi * acc[0]; o0.y += wi * acc[1]; o0.z += wi * acc[2]; o0.w += wi * acc[3];
            o1.x += wi * acc[4]; o1.y += wi * acc[5]; o1.z += wi * acc[6]; o1.w += wi * acc[7];
            *(float4*)dst = o0;
            *(float4*)(dst + 4) = o1;
            __syncthreads();
        }
        float sacc[4][4] = {};
        for (int s4 = 0; s4 < 4; s4++) {
            int j = s4 * 32 + lrow;
            float wk = expf(logw * (float)(127 - j));
            const float* ksrc = g_k + base + (size_t)j * DM + lcol;
            const float* vsrc = g_v + base + (size_t)j * DM + lcol;
            float4 k0 = *(const float4*)ksrc;
            float4 k1 = *(const float4*)(ksrc + 4);
            float4 w0 = *(const float4*)vsrc;
            float4 w1 = *(const float4*)(vsrc + 4);
            k0.x *= wk; k0.y *= wk; k0.z *= wk; k0.w *= wk;
            k1.x *= wk; k1.y *= wk; k1.z *= wk; k1.w *= wk;
            *(float4*)&bufA[lrow][lcol]     = k0;
            *(float4*)&bufA[lrow][lcol + 4] = k1;
            *(float4*)&bufB[lrow][lcol]     = w0;
            *(float4*)&bufB[lrow][lcol + 4] = w1;
            __syncthreads();
#pragma unroll 4
            for (int jj = 0; jj < 32; jj++) {
                float4 ka = *(const float4*)&bufA[jj][td];
                float4 vb = *(const float4*)&bufB[jj][te2];
                float ar[4] = {ka.x,ka.y,ka.z,ka.w};
                float br[4] = {vb.x,vb.y,vb.z,vb.w};
#pragma unroll
                for (int x = 0; x < 4; x++)
#pragma unroll
                    for (int y = 0; y < 4; y++)
                        sacc[x][y] += ar[x] * br[y];
            }
            __syncthreads();
        }
#pragma unroll
        for (int x = 0; x < 4; x++)
#pragma unroll
            for (int y = 0; y < 4; y++)
                state[td + x][te2 + y] = state[td + x][te2 + y] * wC + sacc[x][y];
        __syncthreads();
    }
    for (int idx = tid; idx < 4096; idx += 256) {
        int d = idx >> 6, e = idx & 63;
        state_out[((size_t)(b * NH + h) * 64 + d) * 64 + e] = state[d][e];
    }
}

// ---------------- per-head LN (in place on g_att, output rounded to tf32) ----
__global__ void lnx_kernel(const float* __restrict__ sc,
                           const float* __restrict__ bi)
{
    int w = blockIdx.x * 8 + (threadIdx.x >> 5);
    int lid = threadIdx.x & 31;
    int h = w & 31;
    size_t row = (size_t)(w >> 5);
    float* p = g_att + row * DM + h * 64;
    float x0 = p[lid], x1 = p[lid + 32];
    float s = x0 + x1, q = x0 * x0 + x1 * x1;
#pragma unroll
    for (int o = 16; o > 0; o >>= 1) {
        s += __shfl_xor_sync(0xffffffffu, s, o);
        q += __shfl_xor_sync(0xffffffffu, q, o);
    }
    float mu  = s * (1.f / 64.f);
    float inv = rsqrtf(q * (1.f / 64.f) - mu * mu + 1e-5f);
    p[lid]      = roundtf((x0 - mu) * inv * sc[h * 64 + lid]      + bi[h * 64 + lid]);
    p[lid + 32] = roundtf((x1 - mu) * inv * sc[h * 64 + lid + 32] + bi[h * 64 + lid + 32]);
}

// ---------------- launch ----------------
extern "C" void kernel_launch(void* const* d_in, const int* in_sizes, int n_in,
                              void* d_out, int out_size)
{
    const float* inputs = (const float*)d_in[0];
    const float* tmr    = (const float*)d_in[1];
    const float* tmk    = (const float*)d_in[2];
    const float* tmv    = (const float*)d_in[3];
    const float* Wk     = (const float*)d_in[4];
    const float* Wv     = (const float*)d_in[5];
    const float* Wr     = (const float*)d_in[6];
    const float* Wo     = (const float*)d_in[7];
    const float* tdcy   = (const float*)d_in[8];
    const float* tfirst = (const float*)d_in[9];
    const float* ln1s   = (const float*)d_in[10];
    const float* ln1b   = (const float*)d_in[11];
    const float* lnxs   = (const float*)d_in[12];
    const float* lnxb   = (const float*)d_in[13];

    float* out0      = (float*)d_out;
    float* out_xlast = out0 + (size_t)BZ * SEQ * DM;
    float* out_state = out_xlast + (size_t)BZ * DM;

    const int GSMEM = 4 * STG_FLOATS * 4;   // 81920 B
    cudaFuncSetAttribute(tgemm_kernel<0>, cudaFuncAttributeMaxDynamicSharedMemorySize, GSMEM);
    cudaFuncSetAttribute(tgemm_kernel<1>, cudaFuncAttributeMaxDynamicSharedMemorySize, GSMEM);
    cudaFuncSetAttribute(tgemm_kernel<2>, cudaFuncAttributeMaxDynamicSharedMemorySize, GSMEM);
    cudaFuncSetAttribute(tgemm_kernel<3>, cudaFuncAttributeMaxDynamicSharedMemorySize, GSMEM);

    float* wtr; float* wtk; float* wtv; float* wto;
    cudaGetSymbolAddress((void**)&wtr, g_wtr);
    cudaGetSymbolAddress((void**)&wtk, g_wtk);
    cudaGetSymbolAddress((void**)&wtv, g_wtv);
    cudaGetSymbolAddress((void**)&wto, g_wto);

    transpose4_kernel<<<dim3(64, 64, 4), dim3(32, 8)>>>(Wr, wtr, Wk, wtk, Wv, wtv, Wo, wto);
    lnmix_kernel<<<MROWS, 256>>>(inputs, ln1s, ln1b, tmr, tmk, tmv, out_xlast);

    dim3 g(DM / 128, MROWS / 128);
    tgemm_kernel<0><<<g, 256, GSMEM>>>(wtr, nullptr, nullptr);
    tgemm_kernel<1><<<g, 256, GSMEM>>>(wtk, nullptr, nullptr);
    tgemm_kernel<2><<<g, 256, GSMEM>>>(wtv, nullptr, nullptr);
    rkw_kernel<<<dim3(2, 2, BZ * NC * NH), 256>>>(tdcy, tfirst);
    sep_kernel<<<BZ * NC * NH, 256>>>();
    scan_kernel<<<BZ * NH, 256>>>(tdcy, out_state);
    lnx_kernel<<<(MROWS * NH) / 8, 256>>>(lnxs, lnxb);
    tgemm_kernel<3><<<g, 256, GSMEM>>>(wto, inputs, out0);
}

// round 8
// speedup vs baseline: 1.3033x; 1.2123x over previous
#include <cuda_runtime.h>
#include <cstdint>

#define SEQ   2048
#define DM    2048
#define NH    32
#define DH    64
#define CK    128
#define NC    16
#define BZ    4
#define MROWS (BZ*SEQ)   // 8192
#define BK    16
#define NKT   (DM/BK)    // 128

// ---------------- scratch (device globals; no allocation) ----------------
__device__ float g_rx [BZ*SEQ*DM];
__device__ float g_kx [BZ*SEQ*DM];
__device__ float g_vx [BZ*SEQ*DM];
__device__ float g_r  [BZ*SEQ*DM];
__device__ float g_k  [BZ*SEQ*DM];
__device__ float g_v  [BZ*SEQ*DM];
__device__ float g_att[BZ*SEQ*DM];
__device__ float g_rkw[(size_t)BZ*NC*NH*CK*CK];
__device__ float g_kv   [BZ*NH*NC*DH*DH];   // per-chunk (k*w)^T @ v
__device__ float g_state[BZ*NH*NC*DH*DH];   // state BEFORE each chunk
__device__ float g_wtr[DM*DM];
__device__ float g_wtk[DM*DM];
__device__ float g_wtv[DM*DM];
__device__ float g_wto[DM*DM];

// ---------------- small PTX helpers ----------------
__device__ __forceinline__ unsigned f2tf(float v)
{
    unsigned r;
    asm("cvt.rna.tf32.f32 %0, %1;" : "=r"(r) : "f"(v));
    return r;
}
__device__ __forceinline__ float roundtf(float v) { return __uint_as_float(f2tf(v)); }

__device__ __forceinline__ uint32_t smem_u32(const void* p)
{
    uint32_t a;
    asm("{ .reg .u64 t; cvta.to.shared.u64 t, %1; cvt.u32.u64 %0, t; }" : "=r"(a) : "l"(p));
    return a;
}
template<int N> __device__ __forceinline__ void cp_wait()
{
    asm volatile("cp.async.wait_group %0;" :: "n"(N) : "memory");
}
__device__ __forceinline__ void cp16(uint32_t dst, const void* src)
{
    asm volatile("cp.async.cg.shared.global [%0], [%1], 16;" :: "r"(dst), "l"(src));
}
__device__ __forceinline__ void cp_commit()
{
    asm volatile("cp.async.commit_group;" ::: "memory");
}
__device__ __forceinline__ void mma_tf32(float* c, const unsigned* a, const unsigned* b)
{
    asm volatile(
        "mma.sync.aligned.m16n8k8.row.col.f32.tf32.tf32.f32 "
        "{%0,%1,%2,%3}, {%4,%5,%6,%7}, {%8,%9}, {%0,%1,%2,%3};"
        : "+f"(c[0]), "+f"(c[1]), "+f"(c[2]), "+f"(c[3])
        : "r"(a[0]), "r"(a[1]), "r"(a[2]), "r"(a[3]),
          "r"(b[0]), "r"(b[1]));
}
// one ldmatrix.x4: four 8x4 fp32 tiles (b16 view), 4 regs/lane
__device__ __forceinline__ void ldsm4(unsigned* r, uint32_t addr)
{
    asm volatile("ldmatrix.sync.aligned.m8n8.x4.shared.b16 {%0,%1,%2,%3}, [%4];"
        : "=r"(r[0]), "=r"(r[1]), "=r"(r[2]), "=r"(r[3]) : "r"(addr));
}

// ---------------- fused LN + token-shift mixing ----------------
__global__ void lnmix_kernel(const float* __restrict__ x,
                             const float* __restrict__ sc,
                             const float* __restrict__ bi,
                             const float* __restrict__ tmr,
                             const float* __restrict__ tmk,
                             const float* __restrict__ tmv,
                             float* __restrict__ xlast)
{
    int row = blockIdx.x;
    int t   = row & (SEQ - 1);
    const float* xr = x + (size_t)row * DM;
    float cur[8], prv[8];
    float s0 = 0.f, q0 = 0.f, s1 = 0.f, q1 = 0.f;
#pragma unroll
    for (int i = 0; i < 8; i++) {
        int c = threadIdx.x + i * 256;
        float v = xr[c];
        cur[i] = v; s0 += v; q0 += v * v;
        float u = t ? xr[c - DM] : 0.f;
        prv[i] = u; s1 += u; q1 += u * u;
    }
#pragma unroll
    for (int o = 16; o > 0; o >>= 1) {
        s0 += __shfl_xor_sync(0xffffffffu, s0, o);
        q0 += __shfl_xor_sync(0xffffffffu, q0, o);
        s1 += __shfl_xor_sync(0xffffffffu, s1, o);
        q1 += __shfl_xor_sync(0xffffffffu, q1, o);
    }
    __shared__ float rs0[8], rq0[8], rs1[8], rq1[8];
    int w = threadIdx.x >> 5;
    if ((threadIdx.x & 31) == 0) { rs0[w] = s0; rq0[w] = q0; rs1[w] = s1; rq1[w] = q1; }
    __syncthreads();
    s0 = 0.f; q0 = 0.f; s1 = 0.f; q1 = 0.f;
#pragma unroll
    for (int i = 0; i < 8; i++) { s0 += rs0[i]; q0 += rq0[i]; s1 += rs1[i]; q1 += rq1[i]; }
    float mu0  = s0 * (1.f / DM);
    float inv0 = rsqrtf(q0 * (1.f / DM) - mu0 * mu0 + 1e-5f);
    float mu1  = s1 * (1.f / DM);
    float inv1 = rsqrtf(q1 * (1.f / DM) - mu1 * mu1 + 1e-5f);
    bool last = (t == SEQ - 1);
#pragma unroll
    for (int i = 0; i < 8; i++) {
        int c = threadIdx.x + i * 256;
        float yc = (cur[i] - mu0) * inv0 * sc[c] + bi[c];
        float yp = t ? (prv[i] - mu1) * inv1 * sc[c] + bi[c] : 0.f;
        size_t off = (size_t)row * DM + c;
        float mr = tmr[c], mk = tmk[c], mv = tmv[c];
        g_rx[off] = roundtf(yc * mr + (1.f - mr) * yp);
        g_kx[off] = roundtf(yc * mk + (1.f - mk) * yp);
        g_vx[off] = roundtf(yc * mv + (1.f - mv) * yp);
        if (last) xlast[(row >> 11) * DM + c] = yc;
    }
}

// ---------------- 4 weight transposes in one launch (tf32 rounding) --------
__global__ void transpose4_kernel(const float* __restrict__ s0, float* __restrict__ d0,
                                  const float* __restrict__ s1, float* __restrict__ d1,
                                  const float* __restrict__ s2, float* __restrict__ d2,
                                  const float* __restrict__ s3, float* __restrict__ d3)
{
    const float* src; float* dst;
    switch (blockIdx.z) {
        case 0:  src = s0; dst = d0; break;
        case 1:  src = s1; dst = d1; break;
        case 2:  src = s2; dst = d2; break;
        default: src = s3; dst = d3; break;
    }
    __shared__ float t[32][33];
    int bx = blockIdx.x * 32, by = blockIdx.y * 32;
#pragma unroll
    for (int i = 0; i < 4; i++)
        t[threadIdx.y + i * 8][threadIdx.x] =
            src[(size_t)(by + threadIdx.y + i * 8) * DM + bx + threadIdx.x];
    __syncthreads();
#pragma unroll
    for (int i = 0; i < 4; i++)
        dst[(size_t)(bx + threadIdx.y + i * 8) * DM + by + threadIdx.x] =
            roundtf(t[threadIdx.x][threadIdx.y + i * 8]);
}

// ---------------- tf32 mma.sync GEMM, cp.async 4-stage, ldmatrix frags ----
#define ASTRIDE 20                      // floats per smem row (16 data + 4 pad)
#define STG_FLOATS (2 * 128 * ASTRIDE)  // A tile + B tile per stage = 5120 floats

template<int MODE>
__global__ void __launch_bounds__(256, 2) tgemm_kernel(const float* __restrict__ Bt,
                                                       const float* __restrict__ Add,
                                                       float* __restrict__ Out)
{
    const float* A;
    float* C;
    if constexpr (MODE == 0) { A = g_rx; C = g_r; }
    else if constexpr (MODE == 1) { A = g_kx; C = g_k; }
    else if constexpr (MODE == 2) { A = g_vx; C = g_v; }
    else { A = g_att; C = Out; }

    extern __shared__ float smem[];
    uint32_t sb = smem_u32(smem);
    int tid = threadIdx.x, lane = tid & 31, warp = tid >> 5;
    int r0 = lane >> 2, c0 = lane & 3;
    int wm = (warp >> 2) * 64, wn = (warp & 3) * 32;
    int bm = blockIdx.y * 128, bn = blockIdx.x * 128;

    const float* Ag = A  + (size_t)bm * DM;
    const float* Bg = Bt + (size_t)bn * DM;

    // ldmatrix per-lane row addresses (byte offsets into tile)
    int lane7 = lane & 7;
    uint32_t a_off = (uint32_t)(((wm + ((lane >> 3) & 1) * 8 + lane7) * ASTRIDE
                                + (lane >> 4) * 4) * 4);
    uint32_t b_off = (uint32_t)(((wn + (lane >> 4) * 8 + lane7) * ASTRIDE
                                + ((lane >> 3) & 1) * 4) * 4);

    int cm = tid >> 1, cko = (tid & 1) * 8;   // copy: row, k-offset
    auto copy_stage = [&](int buf, int kt) {
        uint32_t sA = sb + buf * (STG_FLOATS * 4);
        uint32_t sB = sA + 128 * ASTRIDE * 4;
        const float* Ac = Ag + kt * BK + (size_t)cm * DM + cko;
        const float* Bc = Bg + kt * BK + (size_t)cm * DM + cko;
        uint32_t off = cm * (ASTRIDE * 4) + cko * 4;
        cp16(sA + off,      Ac);
        cp16(sA + off + 16, Ac + 4);
        cp16(sB + off,      Bc);
        cp16(sB + off + 16, Bc + 4);
        cp_commit();
    };

    float acc[4][4][4];
#pragma unroll
    for (int i = 0; i < 4; i++)
#pragma unroll
        for (int j = 0; j < 4; j++)
#pragma unroll
            for (int e = 0; e < 4; e++) acc[i][j][e] = 0.f;

    copy_stage(0, 0);
    copy_stage(1, 1);
    copy_stage(2, 2);
    cp_wait<2>();
    __syncthreads();

    for (int kt = 0; kt < NKT; kt++) {
        int buf = kt & 3;
        uint32_t sA = sb + buf * (STG_FLOATS * 4);
        uint32_t sB = sA + 128 * ASTRIDE * 4;
#pragma unroll
        for (int ks = 0; ks < 2; ks++) {
            uint32_t kb = ks * 32;               // k0 * 4 bytes
            unsigned af[4][4], bf[4][2];
#pragma unroll
            for (int i = 0; i < 4; i++)
                ldsm4(af[i], sA + a_off + i * (16 * ASTRIDE * 4) + kb);
            ldsm4(&bf[0][0], sB + b_off + kb);
            ldsm4(&bf[2][0], sB + b_off + 16 * ASTRIDE * 4 + kb);
#pragma unroll
            for (int i = 0; i < 4; i++)
#pragma unroll
                for (int j = 0; j < 4; j++)
                    mma_tf32(acc[i][j], af[i], bf[j]);
        }
        if (kt + 3 < NKT) copy_stage((kt + 3) & 3, kt + 3);
        else              cp_commit();
        cp_wait<2>();
        __syncthreads();
    }

#pragma unroll
    for (int i = 0; i < 4; i++) {
        int row = bm + wm + i * 16 + r0;
#pragma unroll
        for (int j = 0; j < 4; j++) {
            int col = bn + wn + j * 8 + c0 * 2;
            size_t o0 = (size_t)row * DM + col;
            size_t o1 = (size_t)(row + 8) * DM + col;
            float2 v0 = make_float2(acc[i][j][0], acc[i][j][1]);
            float2 v1 = make_float2(acc[i][j][2], acc[i][j][3]);
            if constexpr (MODE == 3) {
                float2 a0 = *(const float2*)(Add + o0);
                float2 a1 = *(const float2*)(Add + o1);
                v0.x += a0.x; v0.y += a0.y;
                v1.x += a1.x; v1.y += a1.y;
            }
            *(float2*)(C + o0) = v0;
            *(float2*)(C + o1) = v1;
        }
    }
}

// ---------------- rkw = (r @ k^T) * mask, per (b,chunk,head), 64x64 tiles --
__global__ void rkw_kernel(const float* __restrict__ tdcy,
                           const float* __restrict__ tfirst)
{
    int jt = blockIdx.x, it = blockIdx.y, bch = blockIdx.z;
    int h = bch & 31;
    int chunk = (bch >> 5) & 15;
    int b = bch >> 9;
    __shared__ float rs[64][68];
    __shared__ float ks[64][68];
    int tid = threadIdx.x;
    int lrow = tid >> 2;
    int lc4  = (tid & 3) * 16;
    size_t rbase = ((size_t)(b*SEQ + chunk*CK + it*64 + lrow)) * DM + h*64 + lc4;
    size_t kbase = ((size_t)(b*SEQ + chunk*CK + jt*64 + lrow)) * DM + h*64 + lc4;
#pragma unroll
    for (int m = 0; m < 4; m++) {
        float4 rv = *(const float4*)(g_r + rbase + m * 4);
        float4 kv = *(const float4*)(g_k + kbase + m * 4);
        int d = lc4 + m * 4;
        rs[d+0][lrow] = rv.x; rs[d+1][lrow] = rv.y; rs[d+2][lrow] = rv.z; rs[d+3][lrow] = rv.w;
        ks[d+0][lrow] = kv.x; ks[d+1][lrow] = kv.y; ks[d+2][lrow] = kv.z; ks[d+3][lrow] = kv.w;
    }
    __syncthreads();
    int tx = tid & 15, ty = tid >> 4;
    float acc[4][4] = {};
#pragma unroll 8
    for (int d = 0; d < 64; d++) {
        float4 a = *(const float4*)&rs[d][ty * 4];
        float4 bq = *(const float4*)&ks[d][tx * 4];
        float ar[4] = {a.x,a.y,a.z,a.w};
        float br[4] = {bq.x,bq.y,bq.z,bq.w};
#pragma unroll
        for (int x = 0; x < 4; x++)
#pragma unroll
            for (int y = 0; y < 4; y++)
                acc[x][y] += ar[x] * br[y];
    }
    float logw = -expf(tdcy[h]);
    float u    =  expf(tfirst[h]);
#pragma unroll
    for (int x = 0; x < 4; x++)
#pragma unroll
        for (int y = 0; y < 4; y++) {
            int i = it * 64 + ty * 4 + x;
            int j = jt * 64 + tx * 4 + y;
            float m;
            if (i > j)      m = expf(logw * (float)(i - j - 1));
            else if (i == j) m = u;
            else             m = 0.f;
            g_rkw[((size_t)bch * CK + i) * CK + j] = acc[x][y] * m;
        }
}

// ---------------- sep = rkw @ v, per (b,chunk,head) ----------------
__global__ void sep_kernel()
{
    int bch = blockIdx.x;
    int h = bch & 31;
    int chunk = (bch >> 5) & 15;
    int b = bch >> 9;
    int tid = threadIdx.x;
    __shared__ float vs[128][64];
    __shared__ float rk[16][132];
    {
        int row = tid >> 1, e0 = (tid & 1) * 32;
        size_t base = ((size_t)(b*SEQ + chunk*CK + row)) * DM + h*64 + e0;
#pragma unroll
        for (int m = 0; m < 8; m++)
            *(float4*)&vs[row][e0 + m * 4] = *(const float4*)(g_v + base + m * 4);
    }
    int ty = tid >> 3, tx = tid & 7;
    float acc[4][8] = {};
    int rrow = tid >> 1, jc = (tid & 1) * 8;
    for (int s = 0; s < 8; s++) {
        const float* src = g_rkw + ((size_t)bch * CK + rrow) * CK + s * 16 + jc;
        float4 r0 = *(const float4*)src;
        float4 r1 = *(const float4*)(src + 4);
        __syncthreads();
        rk[jc+0][rrow] = r0.x; rk[jc+1][rrow] = r0.y; rk[jc+2][rrow] = r0.z; rk[jc+3][rrow] = r0.w;
        rk[jc+4][rrow] = r1.x; rk[jc+5][rrow] = r1.y; rk[jc+6][rrow] = r1.z; rk[jc+7][rrow] = r1.w;
        __syncthreads();
#pragma unroll
        for (int jj = 0; jj < 16; jj++) {
            float4 a  = *(const float4*)&rk[jj][ty * 4];
            float4 b0 = *(const float4*)&vs[s * 16 + jj][tx * 8];
            float4 b1 = *(const float4*)&vs[s * 16 + jj][tx * 8 + 4];
            float ar[4] = {a.x,a.y,a.z,a.w};
            float br[8] = {b0.x,b0.y,b0.z,b0.w,b1.x,b1.y,b1.z,b1.w};
#pragma unroll
            for (int x = 0; x < 4; x++)
#pragma unroll
                for (int e = 0; e < 8; e++)
                    acc[x][e] += ar[x] * br[e];
        }
    }
    size_t obase = ((size_t)(b*SEQ + chunk*CK)) * DM + h*64;
#pragma unroll
    for (int x = 0; x < 4; x++) {
        size_t ro = obase + (size_t)(ty * 4 + x) * DM + tx * 8;
        float4 o0, o1;
        o0.x = acc[x][0]; o0.y = acc[x][1]; o0.z = acc[x][2]; o0.w = acc[x][3];
        o1.x = acc[x][4]; o1.y = acc[x][5]; o1.z = acc[x][6]; o1.w = acc[x][7];
        *(float4*)(g_att + ro)     = o0;
        *(float4*)(g_att + ro + 4) = o1;
    }
}

// ---------------- scan decomposition ----------------
// (1) per-chunk S = (k * w^{C-1-j})^T @ v, fully parallel over (bh, c)
__global__ void kv_kernel(const float* __restrict__ tdcy)
{
    int c = blockIdx.x, bh = blockIdx.y;
    int h = bh & 31, b = bh >> 5;
    int tid = threadIdx.x;
    __shared__ float bufA[32][68];
    __shared__ float bufB[32][68];
    float logw = -expf(tdcy[h]);
    int lrow = tid >> 3, lcol = (tid & 7) * 8;
    int td = (tid >> 4) * 4, te2 = (tid & 15) * 4;
    size_t base = ((size_t)(b*SEQ + c*CK)) * DM + h * 64;
    float sacc[4][4] = {};
    for (int s4 = 0; s4 < 4; s4++) {
        int j = s4 * 32 + lrow;
        float wk = expf(logw * (float)(127 - j));
        const float* ksrc = g_k + base + (size_t)j * DM + lcol;
        const float* vsrc = g_v + base + (size_t)j * DM + lcol;
        float4 k0 = *(const float4*)ksrc;
        float4 k1 = *(const float4*)(ksrc + 4);
        float4 w0 = *(const float4*)vsrc;
        float4 w1 = *(const float4*)(vsrc + 4);
        k0.x *= wk; k0.y *= wk; k0.z *= wk; k0.w *= wk;
        k1.x *= wk; k1.y *= wk; k1.z *= wk; k1.w *= wk;
        *(float4*)&bufA[lrow][lcol]     = k0;
        *(float4*)&bufA[lrow][lcol + 4] = k1;
        *(float4*)&bufB[lrow][lcol]     = w0;
        *(float4*)&bufB[lrow][lcol + 4] = w1;
        __syncthreads();
#pragma unroll 4
        for (int jj = 0; jj < 32; jj++) {
            float4 ka = *(const float4*)&bufA[jj][td];
            float4 vb = *(const float4*)&bufB[jj][te2];
            float ar[4] = {ka.x,ka.y,ka.z,ka.w};
            float br[4] = {vb.x,vb.y,vb.z,vb.w};
#pragma unroll
            for (int x = 0; x < 4; x++)
#pragma unroll
                for (int y = 0; y < 4; y++)
                    sacc[x][y] += ar[x] * br[y];
        }
        __syncthreads();
    }
    size_t obase = ((size_t)bh * NC + c) * 4096;
#pragma unroll
    for (int x = 0; x < 4; x++)
#pragma unroll
        for (int y = 0; y < 4; y++)
            g_kv[obase + (size_t)(td + x) * 64 + te2 + y] = sacc[x][y];
}

// (2) tiny sequential combine: state_c (before chunk c) + final state output
__global__ void combine_kernel(const float* __restrict__ tdcy,
                               float* __restrict__ state_out)
{
    int bh = blockIdx.x;
    int h = bh & 31;
    int tid = threadIdx.x;
    float wC = expf(-expf(tdcy[h]) * 128.f);
    float st[16];
#pragma unroll
    for (int q = 0; q < 16; q++) st[q] = 0.f;
    size_t base = (size_t)bh * NC * 4096;
    for (int c = 0; c < NC; c++) {
        size_t off = base + (size_t)c * 4096;
#pragma unroll
        for (int q = 0; q < 16; q++) {
            size_t idx = off + q * 256 + tid;
            g_state[idx] = st[q];
            st[q] = st[q] * wC + g_kv[idx];
        }
    }
#pragma unroll
    for (int q = 0; q < 16; q++)
        state_out[(size_t)bh * 4096 + q * 256 + tid] = st[q];
}

// (3) bias = (r_c @ state_c) * w^i added into g_att, parallel over (bh, c)
__global__ void bias_kernel(const float* __restrict__ tdcy)
{
    int c = blockIdx.x, bh = blockIdx.y;
    int h = bh & 31, b = bh >> 5;
    int tid = threadIdx.x;
    __shared__ float rs[64][132];   // r transposed [d][i]
    __shared__ float ss[64][68];    // state [d][e]
    {
        int lrow = tid >> 1, lc = (tid & 1) * 32;
        size_t rbase = ((size_t)(b*SEQ + c*CK + lrow)) * DM + h * 64 + lc;
#pragma unroll
        for (int m = 0; m < 8; m++) {
            float4 rv = *(const float4*)(g_r + rbase + m * 4);
            int d = lc + m * 4;
            rs[d+0][lrow] = rv.x; rs[d+1][lrow] = rv.y;
            rs[d+2][lrow] = rv.z; rs[d+3][lrow] = rv.w;
        }
        size_t sbase = ((size_t)bh * NC + c) * 4096;
#pragma unroll
        for (int q = 0; q < 16; q++) {
            int idx = q * 256 + tid;
            ss[idx >> 6][idx & 63] = g_state[sbase + idx];
        }
    }
    __syncthreads();
    int ty = tid >> 3, tx = tid & 7;
    float acc[4][8] = {};
#pragma unroll 4
    for (int d = 0; d < 64; d++) {
        float4 a  = *(const float4*)&rs[d][ty * 4];
        float4 b0 = *(const float4*)&ss[d][tx * 8];
        float4 b1 = *(const float4*)&ss[d][tx * 8 + 4];
        float ar[4] = {a.x,a.y,a.z,a.w};
        float br[8] = {b0.x,b0.y,b0.z,b0.w,b1.x,b1.y,b1.z,b1.w};
#pragma unroll
        for (int x = 0; x < 4; x++)
#pragma unroll
            for (int e = 0; e < 8; e++)
                acc[x][e] += ar[x] * br[e];
    }
    float logw = -expf(tdcy[h]);
    size_t obase = ((size_t)(b*SEQ + c*CK)) * DM + h * 64;
#pragma unroll
    for (int x = 0; x < 4; x++) {
        int i = ty * 4 + x;
        float wi = expf(logw * (float)i);
        float* dst = g_att + obase + (size_t)i * DM + tx * 8;
        float4 o0 = *(float4*)dst;
        float4 o1 = *(float4*)(dst + 4);
        o0.x += wi * acc[x][0]; o0.y += wi * acc[x][1];
        o0.z += wi * acc[x][2]; o0.w += wi * acc[x][3];
        o1.x += wi * acc[x][4]; o1.y += wi * acc[x][5];
        o1.z += wi * acc[x][6]; o1.w += wi * acc[x][7];
        *(float4*)dst = o0;
        *(float4*)(dst + 4) = o1;
    }
}

// ---------------- per-head LN (in place on g_att, output rounded to tf32) ----
__global__ void lnx_kernel(const float* __restrict__ sc,
                           const float* __restrict__ bi)
{
    int w = blockIdx.x * 8 + (threadIdx.x >> 5);
    int lid = threadIdx.x & 31;
    int h = w & 31;
    size_t row = (size_t)(w >> 5);
    float* p = g_att + row * DM + h * 64;
    float x0 = p[lid], x1 = p[lid + 32];
    float s = x0 + x1, q = x0 * x0 + x1 * x1;
#pragma unroll
    for (int o = 16; o > 0; o >>= 1) {
        s += __shfl_xor_sync(0xffffffffu, s, o);
        q += __shfl_xor_sync(0xffffffffu, q, o);
    }
    float mu  = s * (1.f / 64.f);
    float inv = rsqrtf(q * (1.f / 64.f) - mu * mu + 1e-5f);
    p[lid]      = roundtf((x0 - mu) * inv * sc[h * 64 + lid]      + bi[h * 64 + lid]);
    p[lid + 32] = roundtf((x1 - mu) * inv * sc[h * 64 + lid + 32] + bi[h * 64 + lid + 32]);
}

// ---------------- launch ----------------
extern "C" void kernel_launch(void* const* d_in, const int* in_sizes, int n_in,
                              void* d_out, int out_size)
{
    const float* inputs = (const float*)d_in[0];
    const float* tmr    = (const float*)d_in[1];
    const float* tmk    = (const float*)d_in[2];
    const float* tmv    = (const float*)d_in[3];
    const float* Wk     = (const float*)d_in[4];
    const float* Wv     = (const float*)d_in[5];
    const float* Wr     = (const float*)d_in[6];
    const float* Wo     = (const float*)d_in[7];
    const float* tdcy   = (const float*)d_in[8];
    const float* tfirst = (const float*)d_in[9];
    const float* ln1s   = (const float*)d_in[10];
    const float* ln1b   = (const float*)d_in[11];
    const float* lnxs   = (const float*)d_in[12];
    const float* lnxb   = (const float*)d_in[13];

    float* out0      = (float*)d_out;
    float* out_xlast = out0 + (size_t)BZ * SEQ * DM;
    float* out_state = out_xlast + (size_t)BZ * DM;

    const int GSMEM = 4 * STG_FLOATS * 4;   // 81920 B
    cudaFuncSetAttribute(tgemm_kernel<0>, cudaFuncAttributeMaxDynamicSharedMemorySize, GSMEM);
    cudaFuncSetAttribute(tgemm_kernel<1>, cudaFuncAttributeMaxDynamicSharedMemorySize, GSMEM);
    cudaFuncSetAttribute(tgemm_kernel<2>, cudaFuncAttributeMaxDynamicSharedMemorySize, GSMEM);
    cudaFuncSetAttribute(tgemm_kernel<3>, cudaFuncAttributeMaxDynamicSharedMemorySize, GSMEM);

    float* wtr; float* wtk; float* wtv; float* wto;
    cudaGetSymbolAddress((void**)&wtr, g_wtr);
    cudaGetSymbolAddress((void**)&wtk, g_wtk);
    cudaGetSymbolAddress((void**)&wtv, g_wtv);
    cudaGetSymbolAddress((void**)&wto, g_wto);

    transpose4_kernel<<<dim3(64, 64, 4), dim3(32, 8)>>>(Wr, wtr, Wk, wtk, Wv, wtv, Wo, wto);
    lnmix_kernel<<<MROWS, 256>>>(inputs, ln1s, ln1b, tmr, tmk, tmv, out_xlast);

    dim3 g(DM / 128, MROWS / 128);
    tgemm_kernel<0><<<g, 256, GSMEM>>>(wtr, nullptr, nullptr);
    tgemm_kernel<1><<<g, 256, GSMEM>>>(wtk, nullptr, nullptr);
    tgemm_kernel<2><<<g, 256, GSMEM>>>(wtv, nullptr, nullptr);
    rkw_kernel<<<dim3(2, 2, BZ * NC * NH), 256>>>(tdcy, tfirst);
    sep_kernel<<<BZ * NC * NH, 256>>>();
    kv_kernel<<<dim3(NC, BZ * NH), 256>>>(tdcy);
    combine_kernel<<<BZ * NH, 256>>>(tdcy, out_state);
    bias_kernel<<<dim3(NC, BZ * NH), 256>>>(tdcy);
    lnx_kernel<<<(MROWS * NH) / 8, 256>>>(lnxs, lnxb);
    tgemm_kernel<3><<<g, 256, GSMEM>>>(wto, inputs, out0);
}